// round 15
// baseline (speedup 1.0000x reference)
#include <cuda_runtime.h>

// Problem dims (fixed)
#define T_  512
#define B_  256
#define F_  512
#define H_  128
#define G4_ 512   // 4*H
#define A_  8
#define MH_ 64

// Scratch (allocation-free rule: __device__ globals)
__device__ float g_xgates[(size_t)T_ * B_ * G4_];  // x @ W_ih^T + biases
__device__ float g_hseq[(size_t)T_ * B_ * H_];     // per-step hidden states

// ---------------------------------------------------------------------------
// Fast activations (fp32, ~1e-6 rel err)
// ---------------------------------------------------------------------------
__device__ __forceinline__ float sigm_f(float x) {
    return 1.0f / (1.0f + __expf(-x));
}
__device__ __forceinline__ float tanh_f(float x) {
    float e = __expf(2.0f * x);
    return 1.0f - 2.0f / (e + 1.0f);
}

// ---------------------------------------------------------------------------
// Kernel 1: xgates = X[131072,512] @ W_ih^T[512,512] + (b_ih + b_hh)
// 128x128x16 tiled SGEMM, double-buffered (unchanged — known good).
// ---------------------------------------------------------------------------
#define KT 16
__global__ __launch_bounds__(256, 2)
void gemm_xw_kernel(const float* __restrict__ X,
                    const float* __restrict__ Wih,
                    const float* __restrict__ bih,
                    const float* __restrict__ bhh)
{
    __shared__ float As[2][KT * 128];
    __shared__ float Bs[2][KT * 128];

    const int tid = threadIdx.x;
    const int bm  = blockIdx.x >> 2;
    const int bn  = blockIdx.x & 3;
    const int m0  = bm * 128;
    const int g0  = bn * 128;

    const int tm = tid >> 4;
    const int tn = tid & 15;

    const int lrow = tid >> 1;
    const int lk   = (tid & 1) * 8;

    const float* Xp = X   + (size_t)(m0 + lrow) * F_ + lk;
    const float* Wp = Wih + (size_t)(g0 + lrow) * F_ + lk;

    float acc[8][8];
#pragma unroll
    for (int i = 0; i < 8; i++)
#pragma unroll
        for (int j = 0; j < 8; j++) acc[i][j] = 0.0f;

    float bias[8];
#pragma unroll
    for (int j = 0; j < 8; j++) {
        int g = g0 + tn * 8 + j;
        bias[j] = bih[g] + bhh[g];
    }

    float4 ra0 = *reinterpret_cast<const float4*>(Xp);
    float4 ra1 = *reinterpret_cast<const float4*>(Xp + 4);
    float4 rb0 = *reinterpret_cast<const float4*>(Wp);
    float4 rb1 = *reinterpret_cast<const float4*>(Wp + 4);
    {
        float av[8] = {ra0.x, ra0.y, ra0.z, ra0.w, ra1.x, ra1.y, ra1.z, ra1.w};
        float bv[8] = {rb0.x, rb0.y, rb0.z, rb0.w, rb1.x, rb1.y, rb1.z, rb1.w};
#pragma unroll
        for (int q = 0; q < 8; q++) {
            As[0][(lk + q) * 128 + lrow] = av[q];
            Bs[0][(lk + q) * 128 + lrow] = bv[q];
        }
    }
    __syncthreads();

    const int NT = F_ / KT;
#pragma unroll 1
    for (int kt = 0; kt < NT; kt++) {
        const int cur = kt & 1;

        if (kt + 1 < NT) {
            const float* xn = Xp + (kt + 1) * KT;
            const float* wn = Wp + (kt + 1) * KT;
            ra0 = *reinterpret_cast<const float4*>(xn);
            ra1 = *reinterpret_cast<const float4*>(xn + 4);
            rb0 = *reinterpret_cast<const float4*>(wn);
            rb1 = *reinterpret_cast<const float4*>(wn + 4);
        }

        const float* Ac = As[cur];
        const float* Bc = Bs[cur];
#pragma unroll
        for (int k = 0; k < KT; k++) {
            float a[8], b[8];
            float4 a0 = *reinterpret_cast<const float4*>(Ac + k * 128 + tm * 8);
            float4 a1 = *reinterpret_cast<const float4*>(Ac + k * 128 + tm * 8 + 4);
            float4 b0 = *reinterpret_cast<const float4*>(Bc + k * 128 + tn * 8);
            float4 b1 = *reinterpret_cast<const float4*>(Bc + k * 128 + tn * 8 + 4);
            a[0]=a0.x; a[1]=a0.y; a[2]=a0.z; a[3]=a0.w; a[4]=a1.x; a[5]=a1.y; a[6]=a1.z; a[7]=a1.w;
            b[0]=b0.x; b[1]=b0.y; b[2]=b0.z; b[3]=b0.w; b[4]=b1.x; b[5]=b1.y; b[6]=b1.z; b[7]=b1.w;
#pragma unroll
            for (int i = 0; i < 8; i++)
#pragma unroll
                for (int j = 0; j < 8; j++)
                    acc[i][j] = fmaf(a[i], b[j], acc[i][j]);
        }

        if (kt + 1 < NT) {
            const int nxt = cur ^ 1;
            float av[8] = {ra0.x, ra0.y, ra0.z, ra0.w, ra1.x, ra1.y, ra1.z, ra1.w};
            float bv[8] = {rb0.x, rb0.y, rb0.z, rb0.w, rb1.x, rb1.y, rb1.z, rb1.w};
#pragma unroll
            for (int q = 0; q < 8; q++) {
                As[nxt][(lk + q) * 128 + lrow] = av[q];
                Bs[nxt][(lk + q) * 128 + lrow] = bv[q];
            }
        }
        __syncthreads();
    }

#pragma unroll
    for (int i = 0; i < 8; i++) {
        int m = m0 + tm * 8 + i;
        float4 o0 = make_float4(acc[i][0] + bias[0], acc[i][1] + bias[1],
                                acc[i][2] + bias[2], acc[i][3] + bias[3]);
        float4 o1 = make_float4(acc[i][4] + bias[4], acc[i][5] + bias[5],
                                acc[i][6] + bias[6], acc[i][7] + bias[7]);
        float* dst = g_xgates + (size_t)m * G4_ + g0 + tn * 8;
        *reinterpret_cast<float4*>(dst)     = o0;
        *reinterpret_cast<float4*>(dst + 4) = o1;
    }
}

// ---------------------------------------------------------------------------
// Kernel 2: persistent masked-LSTM — R11 fat-thread layout + SHUFFLE exchange.
// Grid = 128 blocks x 256 threads; block owns batch rows {2*bx, 2*bx+1}.
// Thread tid -> (col = tid>>1, lo = tid&1). It computes gates
//   gA = col + lo*128   (i-gate if lo=0, f-gate if lo=1)
//   gB = gA + 256       (g-gate if lo=0, o-gate if lo=1)
// for BOTH batch rows (h broadcast reused, exactly as R11). The 4 gates of
// column `col` end up in adjacent lanes (2*col, 2*col+1): two shfl_xor(1)
// ops deliver them — no gs smem exchange, ONE __syncthreads per step
// (h published via parity-double-buffered rows). Thread owns state
// (col, row=lo). W_hh cols 0..79 in registers (160 regs), cols 80..127 in
// smem — identical footprint and broadcast pattern to R11.
//
// Dynamic smem (floats):
//   [0     , 24576) Wsm4 : float4[12*512], Wsm4[k4*512+g] = W_hh[g][80+4k4..+3]
//   [24576 , 25600) done_s[1024]  (t-major, 2 rows)
//   [25600 , 26128) hbuf[2 parity][2 rows][132]  (pad 132 kills bank alias)
// total = 26128 floats = 104512 bytes
// ---------------------------------------------------------------------------
#define KREG 80
#define KR4  (KREG / 4)        // 20
#define KS4  ((H_ - KREG) / 4) // 12

__global__ __launch_bounds__(256, 1)
void lstm_kernel(const float* __restrict__ done,
                 const float* __restrict__ h0,
                 const float* __restrict__ c0,
                 const float* __restrict__ Whh,
                 float* __restrict__ hT,
                 float* __restrict__ cT)
{
    extern __shared__ float sm[];
    float4* Wsm4   = reinterpret_cast<float4*>(sm);   // [KS4*512] float4
    float*  done_s = sm + 24576;                      // [1024]
    float*  hbuf   = sm + 25600;                      // [2][2][132]

    const int tid  = threadIdx.x;
    const int col  = tid >> 1;       // 0..127
    const int lo   = tid & 1;        // lane-pair role
    const int b0   = blockIdx.x * 2;
    const int brow = b0 + lo;        // this thread's state row

    const int gA = col + lo * 128;   // i (lo=0) / f (lo=1)
    const int gB = gA + 256;         // g (lo=0) / o (lo=1)

    // Register W: rows gA, gB, cols 0..KREG-1 ; smem W: cols KREG..127
    float WA[KREG], WB[KREG];
    {
        const float4* wrA = reinterpret_cast<const float4*>(Whh + (size_t)gA * H_);
        const float4* wrB = reinterpret_cast<const float4*>(Whh + (size_t)gB * H_);
#pragma unroll
        for (int k4 = 0; k4 < KR4; k4++) {
            float4 a = wrA[k4];
            WA[4*k4+0] = a.x; WA[4*k4+1] = a.y; WA[4*k4+2] = a.z; WA[4*k4+3] = a.w;
            float4 b = wrB[k4];
            WB[4*k4+0] = b.x; WB[4*k4+1] = b.y; WB[4*k4+2] = b.z; WB[4*k4+3] = b.w;
        }
#pragma unroll
        for (int k4 = 0; k4 < KS4; k4++) {
            Wsm4[k4 * 512 + gA] = wrA[KR4 + k4];
            Wsm4[k4 * 512 + gB] = wrB[KR4 + k4];
        }
    }
    // done-mask preload (t-major, 2 rows)
    for (int idx = tid; idx < 2 * T_; idx += 256) {
        int t = idx >> 1, bi2 = idx & 1;
        done_s[idx] = done[(size_t)t * B_ + b0 + bi2];
    }

    // init state (col, row lo); mask for t=0; publish into parity 0
    float creg;
    {
        float m = 1.0f - done[(size_t)0 * B_ + brow];
        float hreg = h0[(size_t)brow * H_ + col];
        creg = c0[(size_t)brow * H_ + col] * m;
        hbuf[0 * 264 + lo * 132 + col] = hreg * m;
    }
    __syncthreads();

    // xg for current step: 2 gates x 2 rows, prefetched one step ahead
    const size_t step_stride = (size_t)B_ * G4_;
    const float* xg_base = g_xgates + (size_t)b0 * G4_;
    float xgA0 = xg_base[gA];
    float xgA1 = xg_base[G4_ + gA];
    float xgB0 = xg_base[gB];
    float xgB1 = xg_base[G4_ + gB];

    float hfin = 0.0f, cfin = 0.0f;

#pragma unroll 1
    for (int t = 0; t < T_; t++) {
        const int par = t & 1;
        const float4* h0v = reinterpret_cast<const float4*>(hbuf + par * 264);
        const float4* h1v = reinterpret_cast<const float4*>(hbuf + par * 264 + 132);

        // prefetch next step's xg
        const int tnx = (t + 1 < T_) ? (t + 1) : t;
        const float* xn = xg_base + (size_t)tnx * step_stride;
        float nxA0 = xn[gA];
        float nxA1 = xn[G4_ + gA];
        float nxB0 = xn[gB];
        float nxB1 = xn[G4_ + gB];

        // ---- 4 dot products (2 gates x 2 rows), h broadcast reused
        float aA0 = 0.0f, eA0 = 0.0f, aA1 = 0.0f, eA1 = 0.0f;
        float aB0 = 0.0f, eB0 = 0.0f, aB1 = 0.0f, eB1 = 0.0f;

#pragma unroll
        for (int k4 = 0; k4 < KR4; k4++) {
            float4 ha = h0v[k4];
            float4 hb = h1v[k4];
            aA0 = fmaf(WA[4*k4+0], ha.x, aA0);
            eA0 = fmaf(WA[4*k4+1], ha.y, eA0);
            aA0 = fmaf(WA[4*k4+2], ha.z, aA0);
            eA0 = fmaf(WA[4*k4+3], ha.w, eA0);
            aA1 = fmaf(WA[4*k4+0], hb.x, aA1);
            eA1 = fmaf(WA[4*k4+1], hb.y, eA1);
            aA1 = fmaf(WA[4*k4+2], hb.z, aA1);
            eA1 = fmaf(WA[4*k4+3], hb.w, eA1);
            aB0 = fmaf(WB[4*k4+0], ha.x, aB0);
            eB0 = fmaf(WB[4*k4+1], ha.y, eB0);
            aB0 = fmaf(WB[4*k4+2], ha.z, aB0);
            eB0 = fmaf(WB[4*k4+3], ha.w, eB0);
            aB1 = fmaf(WB[4*k4+0], hb.x, aB1);
            eB1 = fmaf(WB[4*k4+1], hb.y, eB1);
            aB1 = fmaf(WB[4*k4+2], hb.z, aB1);
            eB1 = fmaf(WB[4*k4+3], hb.w, eB1);
        }
#pragma unroll 4
        for (int k4 = 0; k4 < KS4; k4++) {
            float4 wA = Wsm4[k4 * 512 + gA];
            float4 wB = Wsm4[k4 * 512 + gB];
            float4 ha = h0v[KR4 + k4];
            float4 hb = h1v[KR4 + k4];
            aA0 = fmaf(wA.x, ha.x, aA0);
            eA0 = fmaf(wA.y, ha.y, eA0);
            aA0 = fmaf(wA.z, ha.z, aA0);
            eA0 = fmaf(wA.w, ha.w, eA0);
            aA1 = fmaf(wA.x, hb.x, aA1);
            eA1 = fmaf(wA.y, hb.y, eA1);
            aA1 = fmaf(wA.z, hb.z, aA1);
            eA1 = fmaf(wA.w, hb.w, eA1);
            aB0 = fmaf(wB.x, ha.x, aB0);
            eB0 = fmaf(wB.y, ha.y, eB0);
            aB0 = fmaf(wB.z, ha.z, aB0);
            eB0 = fmaf(wB.w, ha.w, eB0);
            aB1 = fmaf(wB.x, hb.x, aB1);
            eB1 = fmaf(wB.y, hb.y, eB1);
            aB1 = fmaf(wB.z, hb.z, aB1);
            eB1 = fmaf(wB.w, hb.w, eB1);
        }

        // full gate pre-activations (incl. xg) for this thread's 2 gates x 2 rows
        float gateA_r0 = aA0 + eA0 + xgA0;
        float gateA_r1 = aA1 + eA1 + xgA1;
        float gateB_r0 = aB0 + eB0 + xgB0;
        float gateB_r1 = aB1 + eB1 + xgB1;

        xgA0 = nxA0; xgA1 = nxA1; xgB0 = nxB0; xgB1 = nxB1;

        // ---- pair exchange: lane 2c holds (i,g) both rows, lane 2c+1 (f,o).
        // Each thread keeps its own row's values, swaps the other row's.
        float sendA = lo ? gateA_r0 : gateA_r1;
        float sendB = lo ? gateB_r0 : gateB_r1;
        float recvA = __shfl_xor_sync(0xffffffffu, sendA, 1);
        float recvB = __shfl_xor_sync(0xffffffffu, sendB, 1);

        float gi = lo ? recvA    : gateA_r0;
        float gf = lo ? gateA_r1 : recvA;
        float gg = lo ? recvB    : gateB_r0;
        float go = lo ? gateB_r1 : recvB;

        // ---- state update (register-local)
        float iv = sigm_f(gi);
        float fv = sigm_f(gf);
        float gv = tanh_f(gg);
        float ov = sigm_f(go);
        creg = fmaf(fv, creg, iv * gv);
        float hv = ov * tanh_f(creg);
        g_hseq[((size_t)t * B_ + brow) * H_ + col] = hv;

        if (t + 1 < T_) {
            float m = 1.0f - done_s[(t + 1) * 2 + lo];
            creg *= m;
            hbuf[(par ^ 1) * 264 + lo * 132 + col] = hv * m;
        } else {
            hfin = hv;
            cfin = creg;
        }
        __syncthreads();   // single barrier per step: h(t+1) published
    }

    hT[(size_t)brow * H_ + col] = hfin;
    cT[(size_t)brow * H_ + col] = cfin;
}

// ---------------------------------------------------------------------------
// Kernel 3: heads (unchanged, known good).
// ---------------------------------------------------------------------------
__global__ __launch_bounds__(256, 1)
void heads_kernel(const float* __restrict__ Wp1, const float* __restrict__ bp1,
                  const float* __restrict__ Wp2, const float* __restrict__ bp2,
                  const float* __restrict__ Wv1, const float* __restrict__ bv1,
                  const float* __restrict__ Wv2, const float* __restrict__ bv2,
                  float* __restrict__ out)
{
    extern __shared__ float sm[];
    float* h_s  = sm;            // [256][129]
    float* wp1  = sm + 33024;
    float* wv1  = sm + 41216;
    float* wp2  = sm + 49408;
    float* wv2  = sm + 49920;
    float* sbp1 = sm + 49984;
    float* sbv1 = sm + 50048;

    const int tid = threadIdx.x;
    const size_t row0 = (size_t)blockIdx.x * 256;

    for (int idx = tid; idx < 256 * 32; idx += 256) {
        int r  = idx >> 5;
        int c4 = idx & 31;
        float4 v = reinterpret_cast<const float4*>(g_hseq + (row0 + r) * H_)[c4];
        float* dst = h_s + r * 129 + c4 * 4;
        dst[0] = v.x; dst[1] = v.y; dst[2] = v.z; dst[3] = v.w;
    }
    for (int idx = tid; idx < H_ * MH_; idx += 256) {
        wp1[idx] = Wp1[idx];
        wv1[idx] = Wv1[idx];
    }
    for (int idx = tid; idx < MH_ * A_; idx += 256) wp2[idx] = Wp2[idx];
    if (tid < 64) {
        wv2[tid]  = Wv2[tid];
        sbp1[tid] = bp1[tid];
        sbv1[tid] = bv1[tid];
    }
    __syncthreads();

    float ap[64], av[64];
#pragma unroll
    for (int i = 0; i < 64; i++) { ap[i] = 0.0f; av[i] = 0.0f; }

    const float*  hrow = h_s + tid * 129;
    const float4* wp1v = reinterpret_cast<const float4*>(wp1);
    const float4* wv1v = reinterpret_cast<const float4*>(wv1);

#pragma unroll 1
    for (int k = 0; k < H_; k++) {
        float hk = hrow[k];
#pragma unroll
        for (int m4 = 0; m4 < 16; m4++) {
            float4 wp = wp1v[k * 16 + m4];
            float4 wv = wv1v[k * 16 + m4];
            ap[m4 * 4 + 0] = fmaf(hk, wp.x, ap[m4 * 4 + 0]);
            ap[m4 * 4 + 1] = fmaf(hk, wp.y, ap[m4 * 4 + 1]);
            ap[m4 * 4 + 2] = fmaf(hk, wp.z, ap[m4 * 4 + 2]);
            ap[m4 * 4 + 3] = fmaf(hk, wp.w, ap[m4 * 4 + 3]);
            av[m4 * 4 + 0] = fmaf(hk, wv.x, av[m4 * 4 + 0]);
            av[m4 * 4 + 1] = fmaf(hk, wv.y, av[m4 * 4 + 1]);
            av[m4 * 4 + 2] = fmaf(hk, wv.z, av[m4 * 4 + 2]);
            av[m4 * 4 + 3] = fmaf(hk, wv.w, av[m4 * 4 + 3]);
        }
    }

    float lg[8];
#pragma unroll
    for (int a = 0; a < 8; a++) lg[a] = bp2[a];
    float v = bv2[0];

#pragma unroll
    for (int mh = 0; mh < 64; mh++) {
        float tp = tanh_f(ap[mh] + sbp1[mh]);
        float tv = tanh_f(av[mh] + sbv1[mh]);
        v = fmaf(tv, wv2[mh], v);
#pragma unroll
        for (int a = 0; a < 8; a++)
            lg[a] = fmaf(tp, wp2[mh * 8 + a], lg[a]);
    }

    float* orow = out + (row0 + tid) * 9;
#pragma unroll
    for (int a = 0; a < 8; a++) orow[a] = lg[a];
    orow[8] = v;
}

// ---------------------------------------------------------------------------
// Launch
// ---------------------------------------------------------------------------
extern "C" void kernel_launch(void* const* d_in, const int* in_sizes, int n_in,
                              void* d_out, int out_size)
{
    (void)in_sizes; (void)n_in; (void)out_size;

    const float* x    = (const float*)d_in[0];
    const float* done = (const float*)d_in[1];
    const float* h0   = (const float*)d_in[2];
    const float* c0   = (const float*)d_in[3];
    const float* Wih  = (const float*)d_in[4];
    const float* Whh  = (const float*)d_in[5];
    const float* bih  = (const float*)d_in[6];
    const float* bhh  = (const float*)d_in[7];
    const float* Wp1  = (const float*)d_in[8];
    const float* bp1  = (const float*)d_in[9];
    const float* Wp2  = (const float*)d_in[10];
    const float* bp2  = (const float*)d_in[11];
    const float* Wv1  = (const float*)d_in[12];
    const float* bv1  = (const float*)d_in[13];
    const float* Wv2  = (const float*)d_in[14];
    const float* bv2  = (const float*)d_in[15];

    float* out = (float*)d_out;
    float* hT  = out + (size_t)T_ * B_ * (A_ + 1);   // after [T*B, 9]
    float* cT  = hT + (size_t)B_ * H_;

    const int lstm_smem  = 26128 * 4;   // 104512 B
    const int heads_smem = 50112 * 4;   // 200448 B
    cudaFuncSetAttribute(lstm_kernel,  cudaFuncAttributeMaxDynamicSharedMemorySize, lstm_smem);
    cudaFuncSetAttribute(heads_kernel, cudaFuncAttributeMaxDynamicSharedMemorySize, heads_smem);

    // 1) input projection: 1024 m-tiles x 4 n-tiles (double-buffered)
    gemm_xw_kernel<<<4096, 256>>>(x, Wih, bih, bhh);
    // 2) recurrence: 128 persistent blocks, shuffle gate-exchange, 1 barrier/step
    lstm_kernel<<<128, 256, lstm_smem>>>(done, h0, c0, Whh, hT, cT);
    // 3) heads: 512 blocks x 256 rows
    heads_kernel<<<512, 256, heads_smem>>>(Wp1, bp1, Wp2, bp2, Wv1, bv1, Wv2, bv2, out);
}

// round 16
// speedup vs baseline: 1.3735x; 1.3735x over previous
#include <cuda_runtime.h>
#include <cuda_bf16.h>
#include <cstdint>

// Problem dims (fixed)
#define T_  512
#define B_  256
#define F_  512
#define H_  128
#define G4_ 512   // 4*H
#define A_  8
#define MH_ 64

// Scratch (allocation-free rule: __device__ globals)
__device__ float g_xgates[(size_t)T_ * B_ * G4_];  // x @ W_ih^T + biases
__device__ float g_hseq[(size_t)T_ * B_ * H_];     // per-step hidden states

// ---------------------------------------------------------------------------
// Helpers
// ---------------------------------------------------------------------------
__device__ __forceinline__ uint32_t smem_u32(const void* p) {
    uint32_t a;
    asm("{ .reg .u64 t; cvta.to.shared.u64 t, %1; cvt.u32.u64 %0, t; }"
        : "=r"(a) : "l"(p));
    return a;
}
__device__ __forceinline__ void ldsm4(uint32_t* r, uint32_t addr) {
    asm volatile("ldmatrix.sync.aligned.m8n8.x4.shared.b16 {%0,%1,%2,%3}, [%4];"
                 : "=r"(r[0]), "=r"(r[1]), "=r"(r[2]), "=r"(r[3]) : "r"(addr));
}
__device__ __forceinline__ void mma_bf16(float* d,
                                         const uint32_t* a,
                                         uint32_t b0, uint32_t b1) {
    asm volatile(
        "mma.sync.aligned.m16n8k16.row.col.f32.bf16.bf16.f32 "
        "{%0,%1,%2,%3}, {%4,%5,%6,%7}, {%8,%9}, {%0,%1,%2,%3};"
        : "+f"(d[0]), "+f"(d[1]), "+f"(d[2]), "+f"(d[3])
        : "r"(a[0]), "r"(a[1]), "r"(a[2]), "r"(a[3]), "r"(b0), "r"(b1));
}
__device__ __forceinline__ unsigned short bf_hi(float v, float& res) {
    __nv_bfloat16 h = __float2bfloat16_rn(v);
    res = v - __bfloat162float(h);
    unsigned short u;
    memcpy(&u, &h, 2);
    return u;
}
__device__ __forceinline__ unsigned short bf_of(float v) {
    __nv_bfloat16 h = __float2bfloat16_rn(v);
    unsigned short u;
    memcpy(&u, &h, 2);
    return u;
}
__device__ __forceinline__ void split_store(char* hip, char* lop, float4 v) {
    float r0, r1, r2, r3;
    unsigned short h0 = bf_hi(v.x, r0), h1 = bf_hi(v.y, r1);
    unsigned short h2 = bf_hi(v.z, r2), h3 = bf_hi(v.w, r3);
    uint2 Hv, Lv;
    Hv.x = (uint32_t)h0 | ((uint32_t)h1 << 16);
    Hv.y = (uint32_t)h2 | ((uint32_t)h3 << 16);
    Lv.x = (uint32_t)bf_of(r0) | ((uint32_t)bf_of(r1) << 16);
    Lv.y = (uint32_t)bf_of(r2) | ((uint32_t)bf_of(r3) << 16);
    *reinterpret_cast<uint2*>(hip) = Hv;
    *reinterpret_cast<uint2*>(lop) = Lv;
}

// ---------------------------------------------------------------------------
// Fast activations (fp32)
// ---------------------------------------------------------------------------
__device__ __forceinline__ float sigm_f(float x) {
    return 1.0f / (1.0f + __expf(-x));
}
__device__ __forceinline__ float tanh_f(float x) {
    float e = __expf(2.0f * x);
    return 1.0f - 2.0f / (e + 1.0f);
}

// ---------------------------------------------------------------------------
// Kernel 1: bf16x3 tensor-core GEMM via classic mma.sync (legacy HMMA path).
//   g_xgates[m,g] = sum_k X[m,k]·W_ih[g,k] + b_ih[g] + b_hh[g]
// X = Xhi+Xlo, W = Whi+Wlo (bf16 rn splits); accumulate hi·hi + hi·lo + lo·hi
// in fp32 via mma.m16n8k16. CTA = 128x128 tile, 8 warps (m32 x n64 each),
// K in 16 double-buffered chunks of 32; fp32->bf16 split fused into loaders.
//
// Smem layout (bytes), stage s at s*40960:
//   AHI 0 | ALO 10240 | BHI 20480 | BLO 30720   (each 128 rows x 80B: 32 bf16
//   data + 8 pad; stride 80 mod 128 => ldmatrix conflict-free)
//   bias fp32[128] at 81920.  Total 82432 B.
// ---------------------------------------------------------------------------
#define STG_   40960
#define AHI_   0
#define ALO_   10240
#define BHI_   20480
#define BLO_   30720
#define GMM_SMEM 82432

__global__ __launch_bounds__(256, 1)
void gemm_mma_kernel(const float* __restrict__ X,
                     const float* __restrict__ Wih,
                     const float* __restrict__ bih,
                     const float* __restrict__ bhh)
{
    extern __shared__ char smc[];
    const uint32_t sb = smem_u32(smc);
    float* bias_s = reinterpret_cast<float*>(smc + 81920);

    const int tid  = threadIdx.x;
    const int lane = tid & 31;
    const int wid  = tid >> 5;
    const int wm   = wid & 3;    // m32 tile index
    const int wn   = wid >> 2;   // n64 tile index

    const int bm = blockIdx.x >> 2;
    const int bn = blockIdx.x & 3;
    const int m0 = bm * 128;
    const int n0 = bn * 128;

    if (tid < 128) bias_s[tid] = bih[n0 + tid] + bhh[n0 + tid];

    // loader mapping: thread covers row lrow, 16 cols (half lhf) per chunk
    const int lrow = tid >> 1;
    const int lhf  = tid & 1;
    const float* Xrow = X   + (size_t)(m0 + lrow) * F_ + lhf * 16;
    const float* Wrow = Wih + (size_t)(n0 + lrow) * F_ + lhf * 16;
    const int stoff = lrow * 80 + lhf * 32;   // byte offset within array

    // ldmatrix per-lane base offsets (bytes within array)
    const int aoff = (wm * 32 + (lane & 15)) * 80 + (lane >> 4) * 16;
    const int boff = (wn * 64 + (lane & 15)) * 80 + (lane >> 4) * 16;

    float d[2][8][4];
#pragma unroll
    for (int i = 0; i < 2; i++)
#pragma unroll
        for (int j = 0; j < 8; j++)
#pragma unroll
            for (int q = 0; q < 4; q++) d[i][j][q] = 0.0f;

    // prologue: chunk 0 -> stage 0
    {
#pragma unroll
        for (int q = 0; q < 4; q++) {
            float4 va = *reinterpret_cast<const float4*>(Xrow + 4 * q);
            float4 vb = *reinterpret_cast<const float4*>(Wrow + 4 * q);
            split_store(smc + AHI_ + stoff + 8 * q, smc + ALO_ + stoff + 8 * q, va);
            split_store(smc + BHI_ + stoff + 8 * q, smc + BLO_ + stoff + 8 * q, vb);
        }
    }
    __syncthreads();

#pragma unroll 1
    for (int c = 0; c < 16; c++) {
        const uint32_t stg = (uint32_t)(c & 1) * STG_;

        // prefetch next chunk into registers
        float4 pa[4], pb[4];
        if (c + 1 < 16) {
            const float* xp = Xrow + (c + 1) * 32;
            const float* wp = Wrow + (c + 1) * 32;
#pragma unroll
            for (int q = 0; q < 4; q++) {
                pa[q] = *reinterpret_cast<const float4*>(xp + 4 * q);
                pb[q] = *reinterpret_cast<const float4*>(wp + 4 * q);
            }
        }

        // mma over 2 k16 steps of this k32 chunk
#pragma unroll
        for (int kk = 0; kk < 2; kk++) {
            const uint32_t kb = kk * 32;
            uint32_t ah0[4], ah1[4], al0[4], al1[4];
            ldsm4(ah0, sb + stg + AHI_ + aoff + kb);
            ldsm4(ah1, sb + stg + AHI_ + aoff + kb + 1280);   // mt=1: +16*80
            ldsm4(al0, sb + stg + ALO_ + aoff + kb);
            ldsm4(al1, sb + stg + ALO_ + aoff + kb + 1280);
#pragma unroll
            for (int j = 0; j < 4; j++) {
                uint32_t bh[4], bl[4];
                ldsm4(bh, sb + stg + BHI_ + boff + j * 1280 + kb);
                ldsm4(bl, sb + stg + BLO_ + boff + j * 1280 + kb);
                // n-tile 2j uses (b[0], b[2]); n-tile 2j+1 uses (b[1], b[3])
                mma_bf16(d[0][2 * j],     ah0, bh[0], bh[2]);   // hi·hi
                mma_bf16(d[0][2 * j + 1], ah0, bh[1], bh[3]);
                mma_bf16(d[1][2 * j],     ah1, bh[0], bh[2]);
                mma_bf16(d[1][2 * j + 1], ah1, bh[1], bh[3]);
                mma_bf16(d[0][2 * j],     ah0, bl[0], bl[2]);   // hi·lo
                mma_bf16(d[0][2 * j + 1], ah0, bl[1], bl[3]);
                mma_bf16(d[1][2 * j],     ah1, bl[0], bl[2]);
                mma_bf16(d[1][2 * j + 1], ah1, bl[1], bl[3]);
                mma_bf16(d[0][2 * j],     al0, bh[0], bh[2]);   // lo·hi
                mma_bf16(d[0][2 * j + 1], al0, bh[1], bh[3]);
                mma_bf16(d[1][2 * j],     al1, bh[0], bh[2]);
                mma_bf16(d[1][2 * j + 1], al1, bh[1], bh[3]);
            }
        }

        // stage next chunk into the other buffer
        if (c + 1 < 16) {
            const uint32_t nst = (uint32_t)((c + 1) & 1) * STG_;
#pragma unroll
            for (int q = 0; q < 4; q++) {
                split_store(smc + nst + AHI_ + stoff + 8 * q,
                            smc + nst + ALO_ + stoff + 8 * q, pa[q]);
                split_store(smc + nst + BHI_ + stoff + 8 * q,
                            smc + nst + BLO_ + stoff + 8 * q, pb[q]);
            }
        }
        __syncthreads();
    }

    // epilogue: D fragments + bias -> g_xgates
    const int gid = lane >> 2;
    const int tig = lane & 3;
#pragma unroll
    for (int mt = 0; mt < 2; mt++) {
#pragma unroll
        for (int nt = 0; nt < 8; nt++) {
            const int r0 = m0 + wm * 32 + mt * 16 + gid;
            const int cl = wn * 64 + nt * 8 + tig * 2;
            const float b0v = bias_s[cl];
            const float b1v = bias_s[cl + 1];
            float2 v0 = make_float2(d[mt][nt][0] + b0v, d[mt][nt][1] + b1v);
            float2 v1 = make_float2(d[mt][nt][2] + b0v, d[mt][nt][3] + b1v);
            *reinterpret_cast<float2*>(g_xgates + (size_t)r0 * G4_ + n0 + cl)       = v0;
            *reinterpret_cast<float2*>(g_xgates + (size_t)(r0 + 8) * G4_ + n0 + cl) = v1;
        }
    }
}

// ---------------------------------------------------------------------------
// Kernel 2: persistent masked-LSTM recurrence — exact R11 layout (best known).
// Grid = 128 blocks x 256 threads; block owns batch rows {2*bx, 2*bx+1}.
// Thread tid computes gates g0=tid and g1=tid+256 for BOTH rows.
// W_hh cols 0..79 in registers, cols 80..127 in smem.
//
// Dynamic smem (floats):
//   [0     , 24576) Wsm4 : float4[12*512]
//   [24576 , 25600) done_s[1024]
//   [25600 , 25856) h_s[2][128]
//   [25856 , 26880) gs [2][512]
// total = 26880 floats = 107520 bytes
// ---------------------------------------------------------------------------
#define KREG 80
#define KR4  (KREG / 4)        // 20
#define KS4  ((H_ - KREG) / 4) // 12

__global__ __launch_bounds__(256, 1)
void lstm_kernel(const float* __restrict__ done,
                 const float* __restrict__ h0,
                 const float* __restrict__ c0,
                 const float* __restrict__ Whh,
                 float* __restrict__ hT,
                 float* __restrict__ cT)
{
    extern __shared__ float sm[];
    float4* Wsm4   = reinterpret_cast<float4*>(sm);   // [KS4*512]
    float*  done_s = sm + 24576;                      // [1024]
    float*  h_s    = sm + 25600;                      // [2][128]
    float*  gs     = sm + 25856;                      // [2][512]

    const int tid = threadIdx.x;
    const int g0  = tid;         // first gate row
    const int g1  = tid + 256;   // second gate row
    const int b0  = blockIdx.x * 2;

    float W0[KREG], W1[KREG];
    {
        const float4* wr0 = reinterpret_cast<const float4*>(Whh + (size_t)g0 * H_);
        const float4* wr1 = reinterpret_cast<const float4*>(Whh + (size_t)g1 * H_);
#pragma unroll
        for (int k4 = 0; k4 < KR4; k4++) {
            float4 a = wr0[k4];
            W0[4*k4+0] = a.x; W0[4*k4+1] = a.y; W0[4*k4+2] = a.z; W0[4*k4+3] = a.w;
            float4 b = wr1[k4];
            W1[4*k4+0] = b.x; W1[4*k4+1] = b.y; W1[4*k4+2] = b.z; W1[4*k4+3] = b.w;
        }
#pragma unroll
        for (int k4 = 0; k4 < KS4; k4++) {
            Wsm4[k4 * 512 + g0] = wr0[KR4 + k4];
            Wsm4[k4 * 512 + g1] = wr1[KR4 + k4];
        }
    }
    for (int idx = tid; idx < 2 * T_; idx += 256) {
        int t = idx >> 1, bi2 = idx & 1;
        done_s[idx] = done[(size_t)t * B_ + b0 + bi2];
    }

    const int bi = tid >> 7;
    const int j  = tid & 127;
    float creg;
    {
        float hreg = h0[(size_t)(b0 + bi) * H_ + j];
        creg = c0[(size_t)(b0 + bi) * H_ + j];
        float m = 1.0f - done[(size_t)0 * B_ + b0 + bi];
        creg *= m;
        h_s[bi * 128 + j] = hreg * m;
    }
    __syncthreads();

    const float4* h0v = reinterpret_cast<const float4*>(h_s);
    const float4* h1v = reinterpret_cast<const float4*>(h_s + 128);

    const size_t step_stride = (size_t)B_ * G4_;
    const float* xg_base = g_xgates + (size_t)b0 * G4_;
    float xg00 = xg_base[g0];
    float xg01 = xg_base[G4_ + g0];
    float xg10 = xg_base[g1];
    float xg11 = xg_base[G4_ + g1];

    float hfin = 0.0f, cfin = 0.0f;

#pragma unroll 1
    for (int t = 0; t < T_; t++) {
        const int tnx = (t + 1 < T_) ? (t + 1) : t;
        const float* xn = xg_base + (size_t)tnx * step_stride;
        float nx00 = xn[g0];
        float nx01 = xn[G4_ + g0];
        float nx10 = xn[g1];
        float nx11 = xn[G4_ + g1];

        {
            float a00 = 0.0f, b00 = 0.0f;
            float a01 = 0.0f, b01 = 0.0f;
            float a10 = 0.0f, b10 = 0.0f;
            float a11 = 0.0f, b11 = 0.0f;

#pragma unroll
            for (int k4 = 0; k4 < KR4; k4++) {
                float4 ha = h0v[k4];
                float4 hb = h1v[k4];
                a00 = fmaf(W0[4*k4+0], ha.x, a00);
                b00 = fmaf(W0[4*k4+1], ha.y, b00);
                a00 = fmaf(W0[4*k4+2], ha.z, a00);
                b00 = fmaf(W0[4*k4+3], ha.w, b00);
                a01 = fmaf(W0[4*k4+0], hb.x, a01);
                b01 = fmaf(W0[4*k4+1], hb.y, b01);
                a01 = fmaf(W0[4*k4+2], hb.z, a01);
                b01 = fmaf(W0[4*k4+3], hb.w, b01);
                a10 = fmaf(W1[4*k4+0], ha.x, a10);
                b10 = fmaf(W1[4*k4+1], ha.y, b10);
                a10 = fmaf(W1[4*k4+2], ha.z, a10);
                b10 = fmaf(W1[4*k4+3], ha.w, b10);
                a11 = fmaf(W1[4*k4+0], hb.x, a11);
                b11 = fmaf(W1[4*k4+1], hb.y, b11);
                a11 = fmaf(W1[4*k4+2], hb.z, a11);
                b11 = fmaf(W1[4*k4+3], hb.w, b11);
            }
#pragma unroll 4
            for (int k4 = 0; k4 < KS4; k4++) {
                float4 w0 = Wsm4[k4 * 512 + g0];
                float4 w1 = Wsm4[k4 * 512 + g1];
                float4 ha = h0v[KR4 + k4];
                float4 hb = h1v[KR4 + k4];
                a00 = fmaf(w0.x, ha.x, a00);
                b00 = fmaf(w0.y, ha.y, b00);
                a00 = fmaf(w0.z, ha.z, a00);
                b00 = fmaf(w0.w, ha.w, b00);
                a01 = fmaf(w0.x, hb.x, a01);
                b01 = fmaf(w0.y, hb.y, b01);
                a01 = fmaf(w0.z, hb.z, a01);
                b01 = fmaf(w0.w, hb.w, b01);
                a10 = fmaf(w1.x, ha.x, a10);
                b10 = fmaf(w1.y, ha.y, b10);
                a10 = fmaf(w1.z, ha.z, a10);
                b10 = fmaf(w1.w, ha.w, b10);
                a11 = fmaf(w1.x, hb.x, a11);
                b11 = fmaf(w1.y, hb.y, b11);
                a11 = fmaf(w1.z, hb.z, a11);
                b11 = fmaf(w1.w, hb.w, b11);
            }
            gs[g0]        = a00 + b00 + xg00;
            gs[512 + g0]  = a01 + b01 + xg01;
            gs[g1]        = a10 + b10 + xg10;
            gs[512 + g1]  = a11 + b11 + xg11;
        }
        __syncthreads();

        xg00 = nx00; xg01 = nx01; xg10 = nx10; xg11 = nx11;

        {
            float gi = gs[bi * 512 +        j];
            float gf = gs[bi * 512 + 128 + j];
            float gg = gs[bi * 512 + 256 + j];
            float go = gs[bi * 512 + 384 + j];
            float iv = sigm_f(gi);
            float fv = sigm_f(gf);
            float gv = tanh_f(gg);
            float ov = sigm_f(go);
            creg = fmaf(fv, creg, iv * gv);
            float hv = ov * tanh_f(creg);
            g_hseq[((size_t)t * B_ + b0 + bi) * H_ + j] = hv;
            if (t + 1 < T_) {
                float m = 1.0f - done_s[(t + 1) * 2 + bi];
                creg *= m;
                h_s[bi * 128 + j] = hv * m;
            } else {
                hfin = hv;
                cfin = creg;
            }
        }
        __syncthreads();
    }

    hT[(size_t)(b0 + bi) * H_ + j] = hfin;
    cT[(size_t)(b0 + bi) * H_ + j] = cfin;
}

// ---------------------------------------------------------------------------
// Kernel 3: heads (unchanged, known good).
// ---------------------------------------------------------------------------
__global__ __launch_bounds__(256, 1)
void heads_kernel(const float* __restrict__ Wp1, const float* __restrict__ bp1,
                  const float* __restrict__ Wp2, const float* __restrict__ bp2,
                  const float* __restrict__ Wv1, const float* __restrict__ bv1,
                  const float* __restrict__ Wv2, const float* __restrict__ bv2,
                  float* __restrict__ out)
{
    extern __shared__ float sm[];
    float* h_s  = sm;            // [256][129]
    float* wp1  = sm + 33024;
    float* wv1  = sm + 41216;
    float* wp2  = sm + 49408;
    float* wv2  = sm + 49920;
    float* sbp1 = sm + 49984;
    float* sbv1 = sm + 50048;

    const int tid = threadIdx.x;
    const size_t row0 = (size_t)blockIdx.x * 256;

    for (int idx = tid; idx < 256 * 32; idx += 256) {
        int r  = idx >> 5;
        int c4 = idx & 31;
        float4 v = reinterpret_cast<const float4*>(g_hseq + (row0 + r) * H_)[c4];
        float* dst = h_s + r * 129 + c4 * 4;
        dst[0] = v.x; dst[1] = v.y; dst[2] = v.z; dst[3] = v.w;
    }
    for (int idx = tid; idx < H_ * MH_; idx += 256) {
        wp1[idx] = Wp1[idx];
        wv1[idx] = Wv1[idx];
    }
    for (int idx = tid; idx < MH_ * A_; idx += 256) wp2[idx] = Wp2[idx];
    if (tid < 64) {
        wv2[tid]  = Wv2[tid];
        sbp1[tid] = bp1[tid];
        sbv1[tid] = bv1[tid];
    }
    __syncthreads();

    float ap[64], av[64];
#pragma unroll
    for (int i = 0; i < 64; i++) { ap[i] = 0.0f; av[i] = 0.0f; }

    const float*  hrow = h_s + tid * 129;
    const float4* wp1v = reinterpret_cast<const float4*>(wp1);
    const float4* wv1v = reinterpret_cast<const float4*>(wv1);

#pragma unroll 1
    for (int k = 0; k < H_; k++) {
        float hk = hrow[k];
#pragma unroll
        for (int m4 = 0; m4 < 16; m4++) {
            float4 wp = wp1v[k * 16 + m4];
            float4 wv = wv1v[k * 16 + m4];
            ap[m4 * 4 + 0] = fmaf(hk, wp.x, ap[m4 * 4 + 0]);
            ap[m4 * 4 + 1] = fmaf(hk, wp.y, ap[m4 * 4 + 1]);
            ap[m4 * 4 + 2] = fmaf(hk, wp.z, ap[m4 * 4 + 2]);
            ap[m4 * 4 + 3] = fmaf(hk, wp.w, ap[m4 * 4 + 3]);
            av[m4 * 4 + 0] = fmaf(hk, wv.x, av[m4 * 4 + 0]);
            av[m4 * 4 + 1] = fmaf(hk, wv.y, av[m4 * 4 + 1]);
            av[m4 * 4 + 2] = fmaf(hk, wv.z, av[m4 * 4 + 2]);
            av[m4 * 4 + 3] = fmaf(hk, wv.w, av[m4 * 4 + 3]);
        }
    }

    float lg[8];
#pragma unroll
    for (int a = 0; a < 8; a++) lg[a] = bp2[a];
    float v = bv2[0];

#pragma unroll
    for (int mh = 0; mh < 64; mh++) {
        float tp = tanh_f(ap[mh] + sbp1[mh]);
        float tv = tanh_f(av[mh] + sbv1[mh]);
        v = fmaf(tv, wv2[mh], v);
#pragma unroll
        for (int a = 0; a < 8; a++)
            lg[a] = fmaf(tp, wp2[mh * 8 + a], lg[a]);
    }

    float* orow = out + (row0 + tid) * 9;
#pragma unroll
    for (int a = 0; a < 8; a++) orow[a] = lg[a];
    orow[8] = v;
}

// ---------------------------------------------------------------------------
// Launch
// ---------------------------------------------------------------------------
extern "C" void kernel_launch(void* const* d_in, const int* in_sizes, int n_in,
                              void* d_out, int out_size)
{
    (void)in_sizes; (void)n_in; (void)out_size;

    const float* x    = (const float*)d_in[0];
    const float* done = (const float*)d_in[1];
    const float* h0   = (const float*)d_in[2];
    const float* c0   = (const float*)d_in[3];
    const float* Wih  = (const float*)d_in[4];
    const float* Whh  = (const float*)d_in[5];
    const float* bih  = (const float*)d_in[6];
    const float* bhh  = (const float*)d_in[7];
    const float* Wp1  = (const float*)d_in[8];
    const float* bp1  = (const float*)d_in[9];
    const float* Wp2  = (const float*)d_in[10];
    const float* bp2  = (const float*)d_in[11];
    const float* Wv1  = (const float*)d_in[12];
    const float* bv1  = (const float*)d_in[13];
    const float* Wv2  = (const float*)d_in[14];
    const float* bv2  = (const float*)d_in[15];

    float* out = (float*)d_out;
    float* hT  = out + (size_t)T_ * B_ * (A_ + 1);   // after [T*B, 9]
    float* cT  = hT + (size_t)B_ * H_;

    const int lstm_smem  = 26880 * 4;   // 107520 B
    const int heads_smem = 50112 * 4;   // 200448 B
    cudaFuncSetAttribute(gemm_mma_kernel, cudaFuncAttributeMaxDynamicSharedMemorySize, GMM_SMEM);
    cudaFuncSetAttribute(lstm_kernel,  cudaFuncAttributeMaxDynamicSharedMemorySize, lstm_smem);
    cudaFuncSetAttribute(heads_kernel, cudaFuncAttributeMaxDynamicSharedMemorySize, heads_smem);

    // 1) input projection on tensor cores (bf16x3 via mma.sync)
    gemm_mma_kernel<<<4096, 256, GMM_SMEM>>>(x, Wih, bih, bhh);
    // 2) recurrence: 128 persistent blocks (R11 layout, best known)
    lstm_kernel<<<128, 256, lstm_smem>>>(done, h0, c0, Whh, hT, cT);
    // 3) heads: 512 blocks x 256 rows
    heads_kernel<<<512, 256, heads_smem>>>(Wp1, bp1, Wp2, bp2, Wv1, bv1, Wv2, bv2, out);
}

// round 17
// speedup vs baseline: 1.5992x; 1.1644x over previous
#include <cuda_runtime.h>
#include <cuda_bf16.h>
#include <cstdint>

// Problem dims (fixed)
#define T_  512
#define B_  256
#define F_  512
#define H_  128
#define G4_ 512   // 4*H
#define A_  8
#define MH_ 64

// Scratch (allocation-free rule: __device__ globals)
__device__ float g_xgates[(size_t)T_ * B_ * G4_];  // x @ W_ih^T + biases
__device__ float g_hseq[(size_t)T_ * B_ * H_];     // per-step hidden states
// Pre-split bf16 operands for the tensor-core GEMM
__device__ __nv_bfloat16 g_Xhi[(size_t)T_ * B_ * F_];
__device__ __nv_bfloat16 g_Xlo[(size_t)T_ * B_ * F_];
__device__ __nv_bfloat16 g_Whi[(size_t)G4_ * F_];
__device__ __nv_bfloat16 g_Wlo[(size_t)G4_ * F_];

// ---------------------------------------------------------------------------
// Helpers
// ---------------------------------------------------------------------------
__device__ __forceinline__ uint32_t smem_u32(const void* p) {
    uint32_t a;
    asm("{ .reg .u64 t; cvta.to.shared.u64 t, %1; cvt.u32.u64 %0, t; }"
        : "=r"(a) : "l"(p));
    return a;
}
__device__ __forceinline__ void ldsm4(uint32_t* r, uint32_t addr) {
    asm volatile("ldmatrix.sync.aligned.m8n8.x4.shared.b16 {%0,%1,%2,%3}, [%4];"
                 : "=r"(r[0]), "=r"(r[1]), "=r"(r[2]), "=r"(r[3]) : "r"(addr));
}
__device__ __forceinline__ void mma_bf16(float* d,
                                         const uint32_t* a,
                                         uint32_t b0, uint32_t b1) {
    asm volatile(
        "mma.sync.aligned.m16n8k16.row.col.f32.bf16.bf16.f32 "
        "{%0,%1,%2,%3}, {%4,%5,%6,%7}, {%8,%9}, {%0,%1,%2,%3};"
        : "+f"(d[0]), "+f"(d[1]), "+f"(d[2]), "+f"(d[3])
        : "r"(a[0]), "r"(a[1]), "r"(a[2]), "r"(a[3]), "r"(b0), "r"(b1));
}
__device__ __forceinline__ void cpa16(uint32_t dst, const void* src) {
    asm volatile("cp.async.ca.shared.global [%0], [%1], 16;"
                 :: "r"(dst), "l"(src) : "memory");
}
#define CPA_COMMIT()   asm volatile("cp.async.commit_group;" ::: "memory")
#define CPA_WAIT(N)    asm volatile("cp.async.wait_group %0;" :: "n"(N) : "memory")

__device__ __forceinline__ unsigned short bf_hi(float v, float& res) {
    __nv_bfloat16 h = __float2bfloat16_rn(v);
    res = v - __bfloat162float(h);
    unsigned short u;
    memcpy(&u, &h, 2);
    return u;
}
__device__ __forceinline__ unsigned short bf_of(float v) {
    __nv_bfloat16 h = __float2bfloat16_rn(v);
    unsigned short u;
    memcpy(&u, &h, 2);
    return u;
}

// ---------------------------------------------------------------------------
// Fast activations (fp32)
// ---------------------------------------------------------------------------
__device__ __forceinline__ float sigm_f(float x) {
    return 1.0f / (1.0f + __expf(-x));
}
__device__ __forceinline__ float tanh_f(float x) {
    float e = __expf(2.0f * x);
    return 1.0f - 2.0f / (e + 1.0f);
}

// ---------------------------------------------------------------------------
// Kernel 0: one-shot fp32 -> bf16 hi/lo split of X and W_ih (memory-bound).
// ---------------------------------------------------------------------------
#define NX4_ ((size_t)T_ * B_ * F_ / 4)   // 16777216 float4s
#define NW4_ ((size_t)G4_ * F_ / 4)       // 65536 float4s

__global__ __launch_bounds__(256)
void convert_kernel(const float* __restrict__ X, const float* __restrict__ W)
{
    size_t idx = (size_t)blockIdx.x * 256 + threadIdx.x;
    if (idx >= NX4_ + NW4_) return;

    const float4* src;
    __nv_bfloat16 *dhi, *dlo;
    size_t off;
    if (idx < NX4_) {
        src = reinterpret_cast<const float4*>(X);
        dhi = g_Xhi; dlo = g_Xlo; off = idx;
    } else {
        src = reinterpret_cast<const float4*>(W);
        dhi = g_Whi; dlo = g_Wlo; off = idx - NX4_;
    }
    float4 v = src[off];
    float r0, r1, r2, r3;
    unsigned short h0 = bf_hi(v.x, r0), h1 = bf_hi(v.y, r1);
    unsigned short h2 = bf_hi(v.z, r2), h3 = bf_hi(v.w, r3);
    uint2 Hv, Lv;
    Hv.x = (uint32_t)h0 | ((uint32_t)h1 << 16);
    Hv.y = (uint32_t)h2 | ((uint32_t)h3 << 16);
    Lv.x = (uint32_t)bf_of(r0) | ((uint32_t)bf_of(r1) << 16);
    Lv.y = (uint32_t)bf_of(r2) | ((uint32_t)bf_of(r3) << 16);
    reinterpret_cast<uint2*>(dhi)[off] = Hv;
    reinterpret_cast<uint2*>(dlo)[off] = Lv;
}

// ---------------------------------------------------------------------------
// Kernel 1: bf16x3 tensor-core GEMM (mma.sync), pre-split operands, cp.async
// staging, 2 CTAs/SM.  g_xgates[m,g] = X·W^T (hi·hi+hi·lo+lo·hi) + biases.
// CTA = 128x128 tile, 8 warps (m32 x n64), K in 16 chunks of 32, 2-stage.
//
// Smem (bytes), stage s at s*40960:
//   AHI 0 | ALO 10240 | BHI 20480 | BLO 30720  (128 rows x 80B: 64B data+16 pad)
//   bias fp32[128] at 81920.  Total 82432 B (x2 CTAs = 164864 < 227KB).
// ---------------------------------------------------------------------------
#define STG_   40960
#define AHI_   0
#define ALO_   10240
#define BHI_   20480
#define BLO_   30720
#define GMM_SMEM 82432

__device__ __forceinline__ void copy_chunk(uint32_t sb_st, int c, int m0, int n0,
                                           int lrow, int lhf)
{
    const size_t eoff = (size_t)c * 32 + lhf * 16;
    const __nv_bfloat16* axh = g_Xhi + (size_t)(m0 + lrow) * F_ + eoff;
    const __nv_bfloat16* axl = g_Xlo + (size_t)(m0 + lrow) * F_ + eoff;
    const __nv_bfloat16* bwh = g_Whi + (size_t)(n0 + lrow) * F_ + eoff;
    const __nv_bfloat16* bwl = g_Wlo + (size_t)(n0 + lrow) * F_ + eoff;
    const uint32_t d = sb_st + lrow * 80 + lhf * 32;
    cpa16(d + AHI_,      axh);
    cpa16(d + AHI_ + 16, axh + 8);
    cpa16(d + ALO_,      axl);
    cpa16(d + ALO_ + 16, axl + 8);
    cpa16(d + BHI_,      bwh);
    cpa16(d + BHI_ + 16, bwh + 8);
    cpa16(d + BLO_,      bwl);
    cpa16(d + BLO_ + 16, bwl + 8);
}

__global__ __launch_bounds__(256, 2)
void gemm_mma_kernel(const float* __restrict__ bih,
                     const float* __restrict__ bhh)
{
    extern __shared__ char smc[];
    const uint32_t sb = smem_u32(smc);
    float* bias_s = reinterpret_cast<float*>(smc + 81920);

    const int tid  = threadIdx.x;
    const int lane = tid & 31;
    const int wid  = tid >> 5;
    const int wm   = wid & 3;    // m32 tile index
    const int wn   = wid >> 2;   // n64 tile index

    const int bm = blockIdx.x >> 2;
    const int bn = blockIdx.x & 3;
    const int m0 = bm * 128;
    const int n0 = bn * 128;

    if (tid < 128) bias_s[tid] = bih[n0 + tid] + bhh[n0 + tid];

    const int lrow = tid >> 1;
    const int lhf  = tid & 1;

    // ldmatrix per-lane base offsets (bytes within array)
    const int aoff = (wm * 32 + (lane & 15)) * 80 + (lane >> 4) * 16;
    const int boff = (wn * 64 + (lane & 15)) * 80 + (lane >> 4) * 16;

    float d[2][8][4];
#pragma unroll
    for (int i = 0; i < 2; i++)
#pragma unroll
        for (int j = 0; j < 8; j++)
#pragma unroll
            for (int q = 0; q < 4; q++) d[i][j][q] = 0.0f;

    // prologue: chunk 0 -> stage 0
    copy_chunk(sb, 0, m0, n0, lrow, lhf);
    CPA_COMMIT();

#pragma unroll 1
    for (int c = 0; c < 16; c++) {
        const uint32_t stg = (uint32_t)(c & 1) * STG_;

        if (c + 1 < 16) {
            copy_chunk(sb + (uint32_t)((c + 1) & 1) * STG_, c + 1, m0, n0, lrow, lhf);
            CPA_COMMIT();
            CPA_WAIT(1);     // chunk c resident; chunk c+1 may still fly
        } else {
            CPA_WAIT(0);
        }
        __syncthreads();

        // mma over 2 k16 steps of this k32 chunk
#pragma unroll
        for (int kk = 0; kk < 2; kk++) {
            const uint32_t kb = kk * 32;
            uint32_t ah0[4], ah1[4], al0[4], al1[4];
            ldsm4(ah0, sb + stg + AHI_ + aoff + kb);
            ldsm4(ah1, sb + stg + AHI_ + aoff + kb + 1280);   // mt=1: +16*80
            ldsm4(al0, sb + stg + ALO_ + aoff + kb);
            ldsm4(al1, sb + stg + ALO_ + aoff + kb + 1280);
#pragma unroll
            for (int j = 0; j < 4; j++) {
                uint32_t bh[4], bl[4];
                ldsm4(bh, sb + stg + BHI_ + boff + j * 1280 + kb);
                ldsm4(bl, sb + stg + BLO_ + boff + j * 1280 + kb);
                mma_bf16(d[0][2 * j],     ah0, bh[0], bh[2]);   // hi·hi
                mma_bf16(d[0][2 * j + 1], ah0, bh[1], bh[3]);
                mma_bf16(d[1][2 * j],     ah1, bh[0], bh[2]);
                mma_bf16(d[1][2 * j + 1], ah1, bh[1], bh[3]);
                mma_bf16(d[0][2 * j],     ah0, bl[0], bl[2]);   // hi·lo
                mma_bf16(d[0][2 * j + 1], ah0, bl[1], bl[3]);
                mma_bf16(d[1][2 * j],     ah1, bl[0], bl[2]);
                mma_bf16(d[1][2 * j + 1], ah1, bl[1], bl[3]);
                mma_bf16(d[0][2 * j],     al0, bh[0], bh[2]);   // lo·hi
                mma_bf16(d[0][2 * j + 1], al0, bh[1], bh[3]);
                mma_bf16(d[1][2 * j],     al1, bh[0], bh[2]);
                mma_bf16(d[1][2 * j + 1], al1, bh[1], bh[3]);
            }
        }
        __syncthreads();   // mma done before next iteration's copy overwrites
    }

    // epilogue: D fragments + bias -> g_xgates
    const int gid = lane >> 2;
    const int tig = lane & 3;
#pragma unroll
    for (int mt = 0; mt < 2; mt++) {
#pragma unroll
        for (int nt = 0; nt < 8; nt++) {
            const int r0 = m0 + wm * 32 + mt * 16 + gid;
            const int cl = wn * 64 + nt * 8 + tig * 2;
            const float b0v = bias_s[cl];
            const float b1v = bias_s[cl + 1];
            float2 v0 = make_float2(d[mt][nt][0] + b0v, d[mt][nt][1] + b1v);
            float2 v1 = make_float2(d[mt][nt][2] + b0v, d[mt][nt][3] + b1v);
            *reinterpret_cast<float2*>(g_xgates + (size_t)r0 * G4_ + n0 + cl)       = v0;
            *reinterpret_cast<float2*>(g_xgates + (size_t)(r0 + 8) * G4_ + n0 + cl) = v1;
        }
    }
}

// ---------------------------------------------------------------------------
// Kernel 2: persistent masked-LSTM recurrence — exact R11 layout (best known).
// ---------------------------------------------------------------------------
#define KREG 80
#define KR4  (KREG / 4)        // 20
#define KS4  ((H_ - KREG) / 4) // 12

__global__ __launch_bounds__(256, 1)
void lstm_kernel(const float* __restrict__ done,
                 const float* __restrict__ h0,
                 const float* __restrict__ c0,
                 const float* __restrict__ Whh,
                 float* __restrict__ hT,
                 float* __restrict__ cT)
{
    extern __shared__ float sm[];
    float4* Wsm4   = reinterpret_cast<float4*>(sm);   // [KS4*512]
    float*  done_s = sm + 24576;                      // [1024]
    float*  h_s    = sm + 25600;                      // [2][128]
    float*  gs     = sm + 25856;                      // [2][512]

    const int tid = threadIdx.x;
    const int g0  = tid;
    const int g1  = tid + 256;
    const int b0  = blockIdx.x * 2;

    float W0[KREG], W1[KREG];
    {
        const float4* wr0 = reinterpret_cast<const float4*>(Whh + (size_t)g0 * H_);
        const float4* wr1 = reinterpret_cast<const float4*>(Whh + (size_t)g1 * H_);
#pragma unroll
        for (int k4 = 0; k4 < KR4; k4++) {
            float4 a = wr0[k4];
            W0[4*k4+0] = a.x; W0[4*k4+1] = a.y; W0[4*k4+2] = a.z; W0[4*k4+3] = a.w;
            float4 b = wr1[k4];
            W1[4*k4+0] = b.x; W1[4*k4+1] = b.y; W1[4*k4+2] = b.z; W1[4*k4+3] = b.w;
        }
#pragma unroll
        for (int k4 = 0; k4 < KS4; k4++) {
            Wsm4[k4 * 512 + g0] = wr0[KR4 + k4];
            Wsm4[k4 * 512 + g1] = wr1[KR4 + k4];
        }
    }
    for (int idx = tid; idx < 2 * T_; idx += 256) {
        int t = idx >> 1, bi2 = idx & 1;
        done_s[idx] = done[(size_t)t * B_ + b0 + bi2];
    }

    const int bi = tid >> 7;
    const int j  = tid & 127;
    float creg;
    {
        float hreg = h0[(size_t)(b0 + bi) * H_ + j];
        creg = c0[(size_t)(b0 + bi) * H_ + j];
        float m = 1.0f - done[(size_t)0 * B_ + b0 + bi];
        creg *= m;
        h_s[bi * 128 + j] = hreg * m;
    }
    __syncthreads();

    const float4* h0v = reinterpret_cast<const float4*>(h_s);
    const float4* h1v = reinterpret_cast<const float4*>(h_s + 128);

    const size_t step_stride = (size_t)B_ * G4_;
    const float* xg_base = g_xgates + (size_t)b0 * G4_;
    float xg00 = xg_base[g0];
    float xg01 = xg_base[G4_ + g0];
    float xg10 = xg_base[g1];
    float xg11 = xg_base[G4_ + g1];

    float hfin = 0.0f, cfin = 0.0f;

#pragma unroll 1
    for (int t = 0; t < T_; t++) {
        const int tnx = (t + 1 < T_) ? (t + 1) : t;
        const float* xn = xg_base + (size_t)tnx * step_stride;
        float nx00 = xn[g0];
        float nx01 = xn[G4_ + g0];
        float nx10 = xn[g1];
        float nx11 = xn[G4_ + g1];

        {
            float a00 = 0.0f, b00 = 0.0f;
            float a01 = 0.0f, b01 = 0.0f;
            float a10 = 0.0f, b10 = 0.0f;
            float a11 = 0.0f, b11 = 0.0f;

#pragma unroll
            for (int k4 = 0; k4 < KR4; k4++) {
                float4 ha = h0v[k4];
                float4 hb = h1v[k4];
                a00 = fmaf(W0[4*k4+0], ha.x, a00);
                b00 = fmaf(W0[4*k4+1], ha.y, b00);
                a00 = fmaf(W0[4*k4+2], ha.z, a00);
                b00 = fmaf(W0[4*k4+3], ha.w, b00);
                a01 = fmaf(W0[4*k4+0], hb.x, a01);
                b01 = fmaf(W0[4*k4+1], hb.y, b01);
                a01 = fmaf(W0[4*k4+2], hb.z, a01);
                b01 = fmaf(W0[4*k4+3], hb.w, b01);
                a10 = fmaf(W1[4*k4+0], ha.x, a10);
                b10 = fmaf(W1[4*k4+1], ha.y, b10);
                a10 = fmaf(W1[4*k4+2], ha.z, a10);
                b10 = fmaf(W1[4*k4+3], ha.w, b10);
                a11 = fmaf(W1[4*k4+0], hb.x, a11);
                b11 = fmaf(W1[4*k4+1], hb.y, b11);
                a11 = fmaf(W1[4*k4+2], hb.z, a11);
                b11 = fmaf(W1[4*k4+3], hb.w, b11);
            }
#pragma unroll 4
            for (int k4 = 0; k4 < KS4; k4++) {
                float4 w0 = Wsm4[k4 * 512 + g0];
                float4 w1 = Wsm4[k4 * 512 + g1];
                float4 ha = h0v[KR4 + k4];
                float4 hb = h1v[KR4 + k4];
                a00 = fmaf(w0.x, ha.x, a00);
                b00 = fmaf(w0.y, ha.y, b00);
                a00 = fmaf(w0.z, ha.z, a00);
                b00 = fmaf(w0.w, ha.w, b00);
                a01 = fmaf(w0.x, hb.x, a01);
                b01 = fmaf(w0.y, hb.y, b01);
                a01 = fmaf(w0.z, hb.z, a01);
                b01 = fmaf(w0.w, hb.w, b01);
                a10 = fmaf(w1.x, ha.x, a10);
                b10 = fmaf(w1.y, ha.y, b10);
                a10 = fmaf(w1.z, ha.z, a10);
                b10 = fmaf(w1.w, ha.w, b10);
                a11 = fmaf(w1.x, hb.x, a11);
                b11 = fmaf(w1.y, hb.y, b11);
                a11 = fmaf(w1.z, hb.z, a11);
                b11 = fmaf(w1.w, hb.w, b11);
            }
            gs[g0]        = a00 + b00 + xg00;
            gs[512 + g0]  = a01 + b01 + xg01;
            gs[g1]        = a10 + b10 + xg10;
            gs[512 + g1]  = a11 + b11 + xg11;
        }
        __syncthreads();

        xg00 = nx00; xg01 = nx01; xg10 = nx10; xg11 = nx11;

        {
            float gi = gs[bi * 512 +        j];
            float gf = gs[bi * 512 + 128 + j];
            float gg = gs[bi * 512 + 256 + j];
            float go = gs[bi * 512 + 384 + j];
            float iv = sigm_f(gi);
            float fv = sigm_f(gf);
            float gv = tanh_f(gg);
            float ov = sigm_f(go);
            creg = fmaf(fv, creg, iv * gv);
            float hv = ov * tanh_f(creg);
            g_hseq[((size_t)t * B_ + b0 + bi) * H_ + j] = hv;
            if (t + 1 < T_) {
                float m = 1.0f - done_s[(t + 1) * 2 + bi];
                creg *= m;
                h_s[bi * 128 + j] = hv * m;
            } else {
                hfin = hv;
                cfin = creg;
            }
        }
        __syncthreads();
    }

    hT[(size_t)(b0 + bi) * H_ + j] = hfin;
    cT[(size_t)(b0 + bi) * H_ + j] = cfin;
}

// ---------------------------------------------------------------------------
// Kernel 3: heads (unchanged, known good).
// ---------------------------------------------------------------------------
__global__ __launch_bounds__(256, 1)
void heads_kernel(const float* __restrict__ Wp1, const float* __restrict__ bp1,
                  const float* __restrict__ Wp2, const float* __restrict__ bp2,
                  const float* __restrict__ Wv1, const float* __restrict__ bv1,
                  const float* __restrict__ Wv2, const float* __restrict__ bv2,
                  float* __restrict__ out)
{
    extern __shared__ float sm[];
    float* h_s  = sm;            // [256][129]
    float* wp1  = sm + 33024;
    float* wv1  = sm + 41216;
    float* wp2  = sm + 49408;
    float* wv2  = sm + 49920;
    float* sbp1 = sm + 49984;
    float* sbv1 = sm + 50048;

    const int tid = threadIdx.x;
    const size_t row0 = (size_t)blockIdx.x * 256;

    for (int idx = tid; idx < 256 * 32; idx += 256) {
        int r  = idx >> 5;
        int c4 = idx & 31;
        float4 v = reinterpret_cast<const float4*>(g_hseq + (row0 + r) * H_)[c4];
        float* dst = h_s + r * 129 + c4 * 4;
        dst[0] = v.x; dst[1] = v.y; dst[2] = v.z; dst[3] = v.w;
    }
    for (int idx = tid; idx < H_ * MH_; idx += 256) {
        wp1[idx] = Wp1[idx];
        wv1[idx] = Wv1[idx];
    }
    for (int idx = tid; idx < MH_ * A_; idx += 256) wp2[idx] = Wp2[idx];
    if (tid < 64) {
        wv2[tid]  = Wv2[tid];
        sbp1[tid] = bp1[tid];
        sbv1[tid] = bv1[tid];
    }
    __syncthreads();

    float ap[64], av[64];
#pragma unroll
    for (int i = 0; i < 64; i++) { ap[i] = 0.0f; av[i] = 0.0f; }

    const float*  hrow = h_s + tid * 129;
    const float4* wp1v = reinterpret_cast<const float4*>(wp1);
    const float4* wv1v = reinterpret_cast<const float4*>(wv1);

#pragma unroll 1
    for (int k = 0; k < H_; k++) {
        float hk = hrow[k];
#pragma unroll
        for (int m4 = 0; m4 < 16; m4++) {
            float4 wp = wp1v[k * 16 + m4];
            float4 wv = wv1v[k * 16 + m4];
            ap[m4 * 4 + 0] = fmaf(hk, wp.x, ap[m4 * 4 + 0]);
            ap[m4 * 4 + 1] = fmaf(hk, wp.y, ap[m4 * 4 + 1]);
            ap[m4 * 4 + 2] = fmaf(hk, wp.z, ap[m4 * 4 + 2]);
            ap[m4 * 4 + 3] = fmaf(hk, wp.w, ap[m4 * 4 + 3]);
            av[m4 * 4 + 0] = fmaf(hk, wv.x, av[m4 * 4 + 0]);
            av[m4 * 4 + 1] = fmaf(hk, wv.y, av[m4 * 4 + 1]);
            av[m4 * 4 + 2] = fmaf(hk, wv.z, av[m4 * 4 + 2]);
            av[m4 * 4 + 3] = fmaf(hk, wv.w, av[m4 * 4 + 3]);
        }
    }

    float lg[8];
#pragma unroll
    for (int a = 0; a < 8; a++) lg[a] = bp2[a];
    float v = bv2[0];

#pragma unroll
    for (int mh = 0; mh < 64; mh++) {
        float tp = tanh_f(ap[mh] + sbp1[mh]);
        float tv = tanh_f(av[mh] + sbv1[mh]);
        v = fmaf(tv, wv2[mh], v);
#pragma unroll
        for (int a = 0; a < 8; a++)
            lg[a] = fmaf(tp, wp2[mh * 8 + a], lg[a]);
    }

    float* orow = out + (row0 + tid) * 9;
#pragma unroll
    for (int a = 0; a < 8; a++) orow[a] = lg[a];
    orow[8] = v;
}

// ---------------------------------------------------------------------------
// Launch
// ---------------------------------------------------------------------------
extern "C" void kernel_launch(void* const* d_in, const int* in_sizes, int n_in,
                              void* d_out, int out_size)
{
    (void)in_sizes; (void)n_in; (void)out_size;

    const float* x    = (const float*)d_in[0];
    const float* done = (const float*)d_in[1];
    const float* h0   = (const float*)d_in[2];
    const float* c0   = (const float*)d_in[3];
    const float* Wih  = (const float*)d_in[4];
    const float* Whh  = (const float*)d_in[5];
    const float* bih  = (const float*)d_in[6];
    const float* bhh  = (const float*)d_in[7];
    const float* Wp1  = (const float*)d_in[8];
    const float* bp1  = (const float*)d_in[9];
    const float* Wp2  = (const float*)d_in[10];
    const float* bp2  = (const float*)d_in[11];
    const float* Wv1  = (const float*)d_in[12];
    const float* bv1  = (const float*)d_in[13];
    const float* Wv2  = (const float*)d_in[14];
    const float* bv2  = (const float*)d_in[15];

    float* out = (float*)d_out;
    float* hT  = out + (size_t)T_ * B_ * (A_ + 1);   // after [T*B, 9]
    float* cT  = hT + (size_t)B_ * H_;

    const int lstm_smem  = 26880 * 4;   // 107520 B
    const int heads_smem = 50112 * 4;   // 200448 B
    cudaFuncSetAttribute(gemm_mma_kernel, cudaFuncAttributeMaxDynamicSharedMemorySize, GMM_SMEM);
    cudaFuncSetAttribute(lstm_kernel,  cudaFuncAttributeMaxDynamicSharedMemorySize, lstm_smem);
    cudaFuncSetAttribute(heads_kernel, cudaFuncAttributeMaxDynamicSharedMemorySize, heads_smem);

    // 0) one-shot bf16 hi/lo split of X and W_ih
    const int nconv = (int)((NX4_ + NW4_ + 255) / 256);
    convert_kernel<<<nconv, 256>>>(x, Wih);
    // 1) input projection on tensor cores (bf16x3, cp.async, 2 CTAs/SM)
    gemm_mma_kernel<<<4096, 256, GMM_SMEM>>>(bih, bhh);
    // 2) recurrence: 128 persistent blocks (R11 layout, best known)
    lstm_kernel<<<128, 256, lstm_smem>>>(done, h0, c0, Whh, hT, cT);
    // 3) heads: 512 blocks x 256 rows
    heads_kernel<<<512, 256, heads_smem>>>(Wp1, bp1, Wp2, bp2, Wv1, bv1, Wv2, bv2, out);
}